// round 1
// baseline (speedup 1.0000x reference)
#include <cuda_runtime.h>
#include <cuda_bf16.h>

// Problem constants (fixed shapes for this problem instance)
#define NN      100000      // total nodes
#define EE      1600000     // total edges
#define NZZ     2400000     // framelet nnz
#define BB      50          // graphs
#define NPG     2000        // nodes per graph
#define BANDS   3
#define HH      64
#define FF      64
#define CRR     6000        // coef rows per graph
#define NCRR    300000
#define CC      10

#define SCAN_B  1024
#define NBLK    ((NN + SCAN_B - 1) / SCAN_B)   // 98

// -------- scratch (static device globals; no runtime allocation) --------
__device__ float g_bufA[NN * HH];     // post-GEMM
__device__ float g_bufB[NN * HH];     // post-aggregation (relu)
__device__ float g_dinv[NN];
__device__ int   g_cnt[NN];
__device__ int   g_rowptr[NN + 1];
__device__ int   g_cursor[NN];
__device__ int   g_cols[EE];
__device__ int   g_bsums[128];
__device__ float g_wnode[NN * BANDS];
__device__ float g_pooled[BB * BANDS * HH];

// ---------------- init ----------------
__global__ void k_zero() {
    int i = blockIdx.x * blockDim.x + threadIdx.x;
    if (i < NN) g_cnt[i] = 0;
    if (i < NN * BANDS) g_wnode[i] = 0.0f;
    if (i < BB * BANDS * HH) g_pooled[i] = 0.0f;
}

// ---------------- degree count ----------------
__global__ void k_count(const int* __restrict__ row) {
    int e = blockIdx.x * blockDim.x + threadIdx.x;
    if (e < EE) atomicAdd(&g_cnt[row[e]], 1);
}

// ---------------- 2-level exclusive scan for CSR rowptr ----------------
__global__ void k_scan1() {
    __shared__ int s[SCAN_B];
    int i = blockIdx.x * SCAN_B + threadIdx.x;
    int v = (i < NN) ? g_cnt[i] : 0;
    s[threadIdx.x] = v;
    __syncthreads();
    for (int off = 1; off < SCAN_B; off <<= 1) {
        int t = (threadIdx.x >= off) ? s[threadIdx.x - off] : 0;
        __syncthreads();
        s[threadIdx.x] += t;
        __syncthreads();
    }
    if (i < NN) g_rowptr[i] = s[threadIdx.x] - v;  // exclusive within block
    if (threadIdx.x == SCAN_B - 1) g_bsums[blockIdx.x] = s[SCAN_B - 1];
}

__global__ void k_scan2() {
    __shared__ int s[128];
    int x = threadIdx.x;
    int v = (x < NBLK) ? g_bsums[x] : 0;
    s[x] = v;
    __syncthreads();
    for (int off = 1; off < 128; off <<= 1) {
        int t = (x >= off) ? s[x - off] : 0;
        __syncthreads();
        s[x] += t;
        __syncthreads();
    }
    if (x < NBLK) g_bsums[x] = s[x] - v;  // exclusive
}

__global__ void k_scan3() {
    int i = blockIdx.x * blockDim.x + threadIdx.x;
    if (i < NN) {
        int rp = g_rowptr[i] + g_bsums[i >> 10];
        g_rowptr[i] = rp;
        g_cursor[i] = rp;
        g_dinv[i]   = rsqrtf((float)(g_cnt[i] + 1));  // +1 self loop
    }
    if (i == 0) g_rowptr[NN] = EE;
}

// ---------------- CSR scatter ----------------
__global__ void k_scatter(const int* __restrict__ row, const int* __restrict__ col) {
    int e = blockIdx.x * blockDim.x + threadIdx.x;
    if (e < EE) {
        int r = row[e];
        int p = atomicAdd(&g_cursor[r], 1);
        g_cols[p] = col[e];
    }
}

// ---------------- dense GEMM: C[N,64] = A[N,64] @ W[64,64] ----------------
__global__ void __launch_bounds__(256) k_gemm(const float* __restrict__ A,
                                              const float* __restrict__ W,
                                              float* __restrict__ C) {
    __shared__ float Ws[64][68];
    __shared__ float As[64][68];   // transposed: As[k][r]
    int tid = threadIdx.x;
    int r0 = blockIdx.x * 64;

    for (int idx = tid; idx < 4096; idx += 256) {
        int k = idx >> 6, j = idx & 63;
        Ws[k][j] = W[idx];
        (void)j;
    }
    for (int idx = tid; idx < 4096; idx += 256) {
        int r = idx >> 6, k = idx & 63;
        int gr = r0 + r;
        As[k][r] = (gr < NN) ? A[gr * 64 + k] : 0.0f;
    }
    __syncthreads();

    int tx = tid & 15, ty = tid >> 4;
    float acc[4][4];
#pragma unroll
    for (int i = 0; i < 4; i++)
#pragma unroll
        for (int j = 0; j < 4; j++) acc[i][j] = 0.0f;

#pragma unroll
    for (int k = 0; k < 64; k++) {
        float4 a = *(const float4*)(&As[k][ty * 4]);
        float4 w = *(const float4*)(&Ws[k][tx * 4]);
        float av[4] = {a.x, a.y, a.z, a.w};
        float wv[4] = {w.x, w.y, w.z, w.w};
#pragma unroll
        for (int i = 0; i < 4; i++)
#pragma unroll
            for (int j = 0; j < 4; j++) acc[i][j] += av[i] * wv[j];
    }

#pragma unroll
    for (int i = 0; i < 4; i++) {
        int gr = r0 + ty * 4 + i;
        if (gr < NN) {
            float4 o = make_float4(acc[i][0], acc[i][1], acc[i][2], acc[i][3]);
            *(float4*)(&C[gr * 64 + tx * 4]) = o;
        }
    }
}

// ------- GCN aggregation: one warp per row, float2 per lane, +bias, relu -------
__global__ void __launch_bounds__(256) k_agg(const float* __restrict__ hin,
                                             const float* __restrict__ bias,
                                             float* __restrict__ hout) {
    int gw = (blockIdx.x * blockDim.x + threadIdx.x) >> 5;
    int lane = threadIdx.x & 31;
    if (gw >= NN) return;
    int r = gw;
    float dr = g_dinv[r];
    const float2* h2 = (const float2*)hin;

    float2 hv = h2[r * 32 + lane];
    float ax = dr * hv.x;      // self loop (dinv[r]^2 after final *dr)
    float ay = dr * hv.y;

    int e0 = g_rowptr[r], e1 = g_rowptr[r + 1];
    for (int e = e0; e < e1; e++) {
        int c = g_cols[e];
        float dc = g_dinv[c];
        float2 hc = h2[c * 32 + lane];
        ax += dc * hc.x;
        ay += dc * hc.y;
    }
    float bx = bias[lane * 2];
    float by = bias[lane * 2 + 1];
    float ox = fmaxf(dr * ax + bx, 0.0f);
    float oy = fmaxf(dr * ay + by, 0.0f);
    ((float2*)hout)[r * 32 + lane] = make_float2(ox, oy);
}

// ------- framelet pass A: per-node per-band weight accumulation -------
__global__ void k_frame(const int* __restrict__ fr, const int* __restrict__ fc,
                        const float* __restrict__ fv, const int* __restrict__ dix) {
    int e = blockIdx.x * blockDim.x + threadIdx.x;
    if (e >= NZZ) return;
    int r = fr[e];
    int c = fc[e];
    float v = fv[e];
    int band = dix[r];
    atomicAdd(&g_wnode[c * BANDS + band], v);
}

// ------- framelet pass B: pooled[g,band,:] = sum_j wnode[j,band]*h2[j,:] -------
#define POOL_CHUNKS 4
__global__ void __launch_bounds__(256) k_pool(const float* __restrict__ h) {
    int g = blockIdx.x / POOL_CHUNKS;
    int chunk = blockIdx.x % POOL_CHUNKS;
    int f = threadIdx.x & 63;
    int sub = threadIdx.x >> 6;
    int base = g * NPG + chunk * (NPG / POOL_CHUNKS);
    int end = base + (NPG / POOL_CHUNKS);

    float a0 = 0.0f, a1 = 0.0f, a2 = 0.0f;
    for (int j = base + sub; j < end; j += 4) {
        float w0 = g_wnode[j * 3 + 0];
        float w1 = g_wnode[j * 3 + 1];
        float w2 = g_wnode[j * 3 + 2];
        float hv = h[j * 64 + f];
        a0 += w0 * hv;
        a1 += w1 * hv;
        a2 += w2 * hv;
    }
    __shared__ float s[4][3][64];
    s[sub][0][f] = a0;
    s[sub][1][f] = a1;
    s[sub][2][f] = a2;
    __syncthreads();
    if (sub == 0) {
#pragma unroll
        for (int b = 0; b < 3; b++) {
            float t = s[0][b][f] + s[1][b][f] + s[2][b][f] + s[3][b][f];
            atomicAdd(&g_pooled[(g * 3 + b) * 64 + f], t);
        }
    }
}

// ------- MLP head: out[g] = relu(xp @ fcW1 + fcb1) @ fcW2 + fcb2 -------
__global__ void __launch_bounds__(64) k_head(const float* __restrict__ fcW1,
                                             const float* __restrict__ fcb1,
                                             const float* __restrict__ fcW2,
                                             const float* __restrict__ fcb2,
                                             float* __restrict__ out) {
    int g = blockIdx.x;
    int t = threadIdx.x;
    __shared__ float xp[BANDS * HH];
    __shared__ float hid[HH];
    for (int i = t; i < BANDS * HH; i += 64) xp[i] = g_pooled[g * (BANDS * HH) + i];
    __syncthreads();
    float acc = fcb1[t];
#pragma unroll 8
    for (int k = 0; k < BANDS * HH; k++) acc += xp[k] * fcW1[k * 64 + t];
    hid[t] = fmaxf(acc, 0.0f);
    __syncthreads();
    if (t < CC) {
        float o = fcb2[t];
#pragma unroll
        for (int k = 0; k < HH; k++) o += hid[k] * fcW2[k * CC + t];
        out[g * CC + t] = o;
    }
}

extern "C" void kernel_launch(void* const* d_in, const int* in_sizes, int n_in,
                              void* d_out, int out_size) {
    (void)in_sizes; (void)n_in; (void)out_size;
    const float* x    = (const float*)d_in[0];
    const int*   ei   = (const int*)d_in[1];
    // d_in[2] = batch (unused), d_in[7] = batch_size (unused)
    const int*   frow = (const int*)d_in[3];
    const int*   fcol = (const int*)d_in[4];
    const float* fval = (const float*)d_in[5];
    const int*   dix  = (const int*)d_in[6];
    const float* W1   = (const float*)d_in[8];
    const float* b1   = (const float*)d_in[9];
    const float* W2   = (const float*)d_in[10];
    const float* b2   = (const float*)d_in[11];
    const float* fcW1 = (const float*)d_in[12];
    const float* fcb1 = (const float*)d_in[13];
    const float* fcW2 = (const float*)d_in[14];
    const float* fcb2 = (const float*)d_in[15];
    float* out = (float*)d_out;

    const int* row = ei;        // edge_index[0]
    const int* col = ei + EE;   // edge_index[1]

    // init + CSR build
    k_zero<<<(NN * BANDS + 255) / 256, 256>>>();
    k_count<<<(EE + 255) / 256, 256>>>(row);
    k_scan1<<<NBLK, SCAN_B>>>();
    k_scan2<<<1, 128>>>();
    k_scan3<<<(NN + 255) / 256, 256>>>();
    k_scatter<<<(EE + 255) / 256, 256>>>(row, col);

    // framelet weight table (independent of GCN output)
    k_frame<<<(NZZ + 255) / 256, 256>>>(frow, fcol, fval, dix);

    // GCN layer 1
    k_gemm<<<(NN + 63) / 64, 256>>>(x, W1, g_bufA);
    k_agg<<<(NN * 32 + 255) / 256, 256>>>(g_bufA, b1, g_bufB);
    // GCN layer 2
    k_gemm<<<(NN + 63) / 64, 256>>>(g_bufB, W2, g_bufA);
    k_agg<<<(NN * 32 + 255) / 256, 256>>>(g_bufA, b2, g_bufB);

    // pooled framelet features + head
    k_pool<<<BB * POOL_CHUNKS, 256>>>(g_bufB);
    k_head<<<BB, 64>>>(fcW1, fcb1, fcW2, fcb2, out);
}